// round 1
// baseline (speedup 1.0000x reference)
#include <cuda_runtime.h>
#include <math.h>

// Problem constants
constexpr int NA = 50000;
constexpr int NT = 25000;
constexpr int DIN = 32;
constexpr int H = 64;
constexpr int E_AA = 800000;
constexpr int E_AT = 400000;
constexpr int E_TA = 400000;

// degree/norm array layout (single contiguous region)
//  [0,NA)            : AA (agent in-degree, +1 self loop)  -> dis_aa
//  [NA,2NA)          : AT src degree over agents           -> dis_at_s
//  [2NA,3NA)         : TA dst degree over agents           -> dis_ta_d
//  [3NA,3NA+NT)      : AT dst degree over targets          -> dis_at_d
//  [3NA+NT,3NA+2NT)  : TA src degree over targets          -> dis_ta_s
constexpr int OFF_AA   = 0;
constexpr int OFF_AT_S = NA;
constexpr int OFF_TA_D = 2 * NA;
constexpr int OFF_AT_D = 3 * NA;
constexpr int OFF_TA_S = 3 * NA + NT;
constexpr int NTOT = 3 * NA + 2 * NT;

// Scratch (device globals; no allocation allowed)
__device__ int   g_cnt[NTOT];
__device__ float g_dis[NTOT];
__device__ float g_h_aa[(size_t)NA * H];
__device__ float g_h_at[(size_t)NA * H];
__device__ float g_h_ta[(size_t)NT * H];
__device__ float g_acc_a[(size_t)NA * H];
__device__ float g_acc_t[(size_t)NT * H];

// ---------------------------------------------------------------------------
__global__ void zero_cnt_kernel() {
    int i = blockIdx.x * blockDim.x + threadIdx.x;
    if (i < NTOT) g_cnt[i] = 0;
}

__global__ void count_kernel(const int* __restrict__ idx, int off, int E) {
    int i = blockIdx.x * blockDim.x + threadIdx.x;
    if (i < E) atomicAdd(&g_cnt[off + idx[i]], 1);
}

__global__ void dis_kernel() {
    int i = blockIdx.x * blockDim.x + threadIdx.x;
    if (i >= NTOT) return;
    int c = g_cnt[i];
    float d;
    if (i < NA) {
        // homo AA: deg = in-degree + 1 self loop
        d = rsqrtf((float)c + 1.0f);
    } else {
        d = (c > 0) ? rsqrtf((float)c) : 0.0f;
    }
    g_dis[i] = d;
}

// out[row, :] = (RELU? relu(x[row,:]) : x[row,:]) @ W   (W is [K, H] row-major)
template <int K, bool RELU>
__global__ void transform_kernel(const float* __restrict__ x,
                                 const float* __restrict__ W,
                                 float* __restrict__ out, int n) {
    __shared__ float Ws[K * H];
    __shared__ float xs[4 * K];
    int tid = threadIdx.x;
    for (int i = tid; i < K * H; i += 256) Ws[i] = W[i];
    int row0 = blockIdx.x * 4;
    for (int i = tid; i < 4 * K; i += 256) {
        int r = i / K, k = i - r * K;
        int row = row0 + r;
        float v = (row < n) ? x[(size_t)row * K + k] : 0.0f;
        if (RELU) v = fmaxf(v, 0.0f);
        xs[i] = v;
    }
    __syncthreads();
    int r = tid >> 6;
    int c = tid & 63;
    int row = row0 + r;
    if (row < n) {
        float acc = 0.0f;
#pragma unroll
        for (int k = 0; k < K; k++) acc = fmaf(xs[r * K + k], Ws[k * H + c], acc);
        out[(size_t)row * H + c] = acc;
    }
}

// acc_a[i,c] = h_self[i,c] * dis_aa[i]^2 + b_self[c] + b_other[c]
__global__ void init_acc_agent_kernel(const float* __restrict__ h_self,
                                      const float* __restrict__ b_self,
                                      const float* __restrict__ b_other) {
    int i = blockIdx.x * blockDim.x + threadIdx.x;
    if (i < NA * H) {
        int node = i >> 6, c = i & 63;
        float d = g_dis[OFF_AA + node];
        g_acc_a[i] = h_self[i] * d * d + b_self[c] + b_other[c];
    }
}

__global__ void init_acc_target_kernel(const float* __restrict__ b) {
    int i = blockIdx.x * blockDim.x + threadIdx.x;
    if (i < NT * H) g_acc_t[i] = b[i & 63];
}

// One warp per edge: gather h[src]*norm, atomicAdd into acc[dst]
__global__ void scatter_kernel(const int* __restrict__ src,
                               const int* __restrict__ dst,
                               const float* __restrict__ dis_s,
                               const float* __restrict__ dis_d,
                               const float* __restrict__ h,
                               float* __restrict__ acc, int E) {
    int idx = blockIdx.x * blockDim.x + threadIdx.x;
    int e = idx >> 5, lane = idx & 31;
    if (e >= E) return;
    int s = src[e], d = dst[e];
    float w = dis_s[s] * dis_d[d];
    const float* hs = h + (size_t)s * H;
    float* od = acc + (size_t)d * H;
    atomicAdd(&od[lane], hs[lane] * w);
    atomicAdd(&od[lane + 32], hs[lane + 32] * w);
}

// One warp per row: out[row,:] = g[row,:] @ Wp + bp   (Wp is [H,2])
__global__ void proj_kernel(const float* __restrict__ g,
                            const float* __restrict__ Wp,
                            const float* __restrict__ bp,
                            float* __restrict__ out, int n) {
    int idx = blockIdx.x * blockDim.x + threadIdx.x;
    int row = idx >> 5, lane = idx & 31;
    if (row >= n) return;
    float g0 = g[(size_t)row * H + lane];
    float g1 = g[(size_t)row * H + lane + 32];
    float p0 = g0 * Wp[lane * 2 + 0] + g1 * Wp[(lane + 32) * 2 + 0];
    float p1 = g0 * Wp[lane * 2 + 1] + g1 * Wp[(lane + 32) * 2 + 1];
#pragma unroll
    for (int o = 16; o; o >>= 1) {
        p0 += __shfl_down_sync(0xFFFFFFFFu, p0, o);
        p1 += __shfl_down_sync(0xFFFFFFFFu, p1, o);
    }
    if (lane == 0) {
        out[(size_t)row * 2 + 0] = p0 + bp[0];
        out[(size_t)row * 2 + 1] = p1 + bp[1];
    }
}

// ---------------------------------------------------------------------------
static inline int cdiv(long long a, int b) { return (int)((a + b - 1) / b); }

extern "C" void kernel_launch(void* const* d_in, const int* in_sizes, int n_in,
                              void* d_out, int out_size) {
    // inputs per metadata order
    const float* x_agent  = (const float*)d_in[1];
    const float* x_target = (const float*)d_in[2];
    const int* src_aa = (const int*)d_in[3];
    const int* dst_aa = (const int*)d_in[4];
    const int* src_at = (const int*)d_in[5];
    const int* dst_at = (const int*)d_in[6];
    const int* src_ta = (const int*)d_in[7];
    const int* dst_ta = (const int*)d_in[8];
    const float* W1_aa = (const float*)d_in[9];
    const float* b1_aa = (const float*)d_in[10];
    const float* W1_at = (const float*)d_in[11];
    const float* b1_at = (const float*)d_in[12];
    const float* W1_ta = (const float*)d_in[13];
    const float* b1_ta = (const float*)d_in[14];
    const float* W2_aa = (const float*)d_in[15];
    const float* b2_aa = (const float*)d_in[16];
    const float* W2_at = (const float*)d_in[17];
    const float* b2_at = (const float*)d_in[18];
    const float* W2_ta = (const float*)d_in[19];
    const float* b2_ta = (const float*)d_in[20];
    const float* Wp_agent  = (const float*)d_in[21];
    const float* bp_agent  = (const float*)d_in[22];
    const float* Wp_target = (const float*)d_in[23];
    const float* bp_target = (const float*)d_in[24];
    float* out = (float*)d_out;

    // resolve scratch symbol addresses (pure API lookups; no work, no alloc)
    void *p_dis, *p_haa, *p_hat, *p_hta, *p_acca, *p_acct;
    cudaGetSymbolAddress(&p_dis,  g_dis);
    cudaGetSymbolAddress(&p_haa,  g_h_aa);
    cudaGetSymbolAddress(&p_hat,  g_h_at);
    cudaGetSymbolAddress(&p_hta,  g_h_ta);
    cudaGetSymbolAddress(&p_acca, g_acc_a);
    cudaGetSymbolAddress(&p_acct, g_acc_t);
    float* dis   = (float*)p_dis;
    float* h_aa  = (float*)p_haa;
    float* h_at  = (float*)p_hat;
    float* h_ta  = (float*)p_hta;
    float* acc_a = (float*)p_acca;
    float* acc_t = (float*)p_acct;

    // ---- degrees / norms (shared by both layers) ----
    zero_cnt_kernel<<<cdiv(NTOT, 256), 256>>>();
    count_kernel<<<cdiv(E_AA, 256), 256>>>(dst_aa, OFF_AA,   E_AA);
    count_kernel<<<cdiv(E_AT, 256), 256>>>(src_at, OFF_AT_S, E_AT);
    count_kernel<<<cdiv(E_TA, 256), 256>>>(dst_ta, OFF_TA_D, E_TA);
    count_kernel<<<cdiv(E_AT, 256), 256>>>(dst_at, OFF_AT_D, E_AT);
    count_kernel<<<cdiv(E_TA, 256), 256>>>(src_ta, OFF_TA_S, E_TA);
    dis_kernel<<<cdiv(NTOT, 256), 256>>>();

    // ---- layer 1 transforms: x @ W1_* ----
    transform_kernel<DIN, false><<<cdiv(NA, 4), 256>>>(x_agent,  W1_aa, h_aa, NA);
    transform_kernel<DIN, false><<<cdiv(NA, 4), 256>>>(x_agent,  W1_at, h_at, NA);
    transform_kernel<DIN, false><<<cdiv(NT, 4), 256>>>(x_target, W1_ta, h_ta, NT);

    // ---- layer 1 aggregate ----
    init_acc_agent_kernel<<<cdiv((long long)NA * H, 256), 256>>>(h_aa, b1_aa, b1_ta);
    init_acc_target_kernel<<<cdiv((long long)NT * H, 256), 256>>>(b1_at);
    scatter_kernel<<<cdiv((long long)E_AA * 32, 256), 256>>>(
        src_aa, dst_aa, dis + OFF_AA,   dis + OFF_AA,   h_aa, acc_a, E_AA);
    scatter_kernel<<<cdiv((long long)E_TA * 32, 256), 256>>>(
        src_ta, dst_ta, dis + OFF_TA_S, dis + OFF_TA_D, h_ta, acc_a, E_TA);
    scatter_kernel<<<cdiv((long long)E_AT * 32, 256), 256>>>(
        src_at, dst_at, dis + OFF_AT_S, dis + OFF_AT_D, h_at, acc_t, E_AT);

    // ---- layer 2 transforms: relu(acc) @ W2_* ----
    transform_kernel<H, true><<<cdiv(NA, 4), 256>>>(acc_a, W2_aa, h_aa, NA);
    transform_kernel<H, true><<<cdiv(NA, 4), 256>>>(acc_a, W2_at, h_at, NA);
    transform_kernel<H, true><<<cdiv(NT, 4), 256>>>(acc_t, W2_ta, h_ta, NT);

    // ---- layer 2 aggregate (reuses acc buffers; stream-ordered after transforms) ----
    init_acc_agent_kernel<<<cdiv((long long)NA * H, 256), 256>>>(h_aa, b2_aa, b2_ta);
    init_acc_target_kernel<<<cdiv((long long)NT * H, 256), 256>>>(b2_at);
    scatter_kernel<<<cdiv((long long)E_AA * 32, 256), 256>>>(
        src_aa, dst_aa, dis + OFF_AA,   dis + OFF_AA,   h_aa, acc_a, E_AA);
    scatter_kernel<<<cdiv((long long)E_TA * 32, 256), 256>>>(
        src_ta, dst_ta, dis + OFF_TA_S, dis + OFF_TA_D, h_ta, acc_a, E_TA);
    scatter_kernel<<<cdiv((long long)E_AT * 32, 256), 256>>>(
        src_at, dst_at, dis + OFF_AT_S, dis + OFF_AT_D, h_at, acc_t, E_AT);

    // ---- output projections ----
    proj_kernel<<<cdiv((long long)NA * 32, 256), 256>>>(acc_a, Wp_agent,  bp_agent,  out, NA);
    proj_kernel<<<cdiv((long long)NT * 32, 256), 256>>>(acc_t, Wp_target, bp_target, out + (size_t)NA * 2, NT);
}

// round 2
// speedup vs baseline: 1.2353x; 1.2353x over previous
#include <cuda_runtime.h>
#include <math.h>

// Problem constants
constexpr int NA = 50000;
constexpr int NT = 25000;
constexpr int DIN = 32;
constexpr int H = 64;
constexpr int E_AA = 800000;
constexpr int E_AT = 400000;
constexpr int E_TA = 400000;

// degree/norm array layout (single contiguous region)
constexpr int OFF_AA   = 0;
constexpr int OFF_AT_S = NA;
constexpr int OFF_TA_D = 2 * NA;
constexpr int OFF_AT_D = 3 * NA;
constexpr int OFF_TA_S = 3 * NA + NT;
constexpr int NTOT = 3 * NA + 2 * NT;

// Scratch (device globals; float4 so gathers/atomics can be 128-bit)
__device__ int    g_cnt[NTOT];
__device__ float  g_dis[NTOT];
__device__ float4 g_h_aa[(size_t)NA * H / 4];
__device__ float4 g_h_at[(size_t)NA * H / 4];
__device__ float4 g_h_ta[(size_t)NT * H / 4];
__device__ float4 g_acc_a[(size_t)NA * H / 4];
__device__ float4 g_acc_t[(size_t)NT * H / 4];

__device__ __forceinline__ void red_add_v4(float4* addr, float4 v) {
    asm volatile("red.global.add.v4.f32 [%0], {%1,%2,%3,%4};"
                 :: "l"(addr), "f"(v.x), "f"(v.y), "f"(v.z), "f"(v.w)
                 : "memory");
}

// ---------------------------------------------------------------------------
__global__ void zero_cnt_kernel() {
    int i = blockIdx.x * blockDim.x + threadIdx.x;
    if (i < NTOT) g_cnt[i] = 0;
}

// All five degree counts in one launch
__global__ void count_all_kernel(const int* __restrict__ dst_aa,
                                 const int* __restrict__ src_at,
                                 const int* __restrict__ dst_at,
                                 const int* __restrict__ src_ta,
                                 const int* __restrict__ dst_ta) {
    int i = blockIdx.x * blockDim.x + threadIdx.x;
    const int* p; int off, j;
    if (i < E_AA)                          { p = dst_aa; off = OFF_AA;   j = i; }
    else if (i < E_AA + E_AT)              { p = src_at; off = OFF_AT_S; j = i - E_AA; }
    else if (i < E_AA + 2 * E_AT)          { p = dst_at; off = OFF_AT_D; j = i - E_AA - E_AT; }
    else if (i < E_AA + 2 * E_AT + E_TA)   { p = src_ta; off = OFF_TA_S; j = i - E_AA - 2 * E_AT; }
    else if (i < E_AA + 2 * E_AT + 2*E_TA) { p = dst_ta; off = OFF_TA_D; j = i - E_AA - 2 * E_AT - E_TA; }
    else return;
    atomicAdd(&g_cnt[off + p[j]], 1);
}

__global__ void dis_kernel() {
    int i = blockIdx.x * blockDim.x + threadIdx.x;
    if (i >= NTOT) return;
    int c = g_cnt[i];
    float d;
    if (i < NA) d = rsqrtf((float)c + 1.0f);                 // homo AA: +1 self loop
    else        d = (c > 0) ? rsqrtf((float)c) : 0.0f;
    g_dis[i] = d;
}

// out[row, :] = (RELU? relu(x[row,:]) : x[row,:]) @ W   (W is [K, H] row-major)
template <int K, bool RELU>
__global__ void transform_kernel(const float* __restrict__ x,
                                 const float* __restrict__ W,
                                 float* __restrict__ out, int n) {
    __shared__ float Ws[K * H];
    __shared__ float xs[4 * K];
    int tid = threadIdx.x;
    for (int i = tid; i < K * H; i += 256) Ws[i] = W[i];
    int row0 = blockIdx.x * 4;
    for (int i = tid; i < 4 * K; i += 256) {
        int r = i / K, k = i - r * K;
        int row = row0 + r;
        float v = (row < n) ? x[(size_t)row * K + k] : 0.0f;
        if (RELU) v = fmaxf(v, 0.0f);
        xs[i] = v;
    }
    __syncthreads();
    int r = tid >> 6;
    int c = tid & 63;
    int row = row0 + r;
    if (row < n) {
        float acc = 0.0f;
#pragma unroll
        for (int k = 0; k < K; k++) acc = fmaf(xs[r * K + k], Ws[k * H + c], acc);
        out[(size_t)row * H + c] = acc;
    }
}

// acc_a[i,c] = h_self[i,c] * dis_aa[i]^2 + b_self[c] + b_other[c]
__global__ void init_acc_agent_kernel(const float* __restrict__ h_self,
                                      const float* __restrict__ b_self,
                                      const float* __restrict__ b_other) {
    int i = blockIdx.x * blockDim.x + threadIdx.x;
    if (i < NA * H) {
        int node = i >> 6, c = i & 63;
        float d = g_dis[OFF_AA + node];
        ((float*)g_acc_a)[i] = h_self[i] * d * d + b_self[c] + b_other[c];
    }
}

__global__ void init_acc_target_kernel(const float* __restrict__ b) {
    int i = blockIdx.x * blockDim.x + threadIdx.x;
    if (i < NT * H) ((float*)g_acc_t)[i] = b[i & 63];
}

// 16 lanes per edge: each lane gathers one float4 of h[src], scales, red.v4 into acc[dst]
__global__ void scatter_kernel(const int* __restrict__ src,
                               const int* __restrict__ dst,
                               const float* __restrict__ dis_s,
                               const float* __restrict__ dis_d,
                               const float4* __restrict__ h,
                               float4* __restrict__ acc, int E) {
    int idx = blockIdx.x * blockDim.x + threadIdx.x;
    int e = idx >> 4, sub = idx & 15;
    if (e >= E) return;
    int s = src[e], d = dst[e];
    float w = dis_s[s] * dis_d[d];
    float4 v = h[(size_t)s * (H / 4) + sub];
    v.x *= w; v.y *= w; v.z *= w; v.w *= w;
    red_add_v4(&acc[(size_t)d * (H / 4) + sub], v);
}

// One warp per row: out[row,:] = g[row,:] @ Wp + bp   (Wp is [H,2])
__global__ void proj_kernel(const float* __restrict__ g,
                            const float* __restrict__ Wp,
                            const float* __restrict__ bp,
                            float* __restrict__ out, int n) {
    int idx = blockIdx.x * blockDim.x + threadIdx.x;
    int row = idx >> 5, lane = idx & 31;
    if (row >= n) return;
    float g0 = g[(size_t)row * H + lane];
    float g1 = g[(size_t)row * H + lane + 32];
    float p0 = g0 * Wp[lane * 2 + 0] + g1 * Wp[(lane + 32) * 2 + 0];
    float p1 = g0 * Wp[lane * 2 + 1] + g1 * Wp[(lane + 32) * 2 + 1];
#pragma unroll
    for (int o = 16; o; o >>= 1) {
        p0 += __shfl_down_sync(0xFFFFFFFFu, p0, o);
        p1 += __shfl_down_sync(0xFFFFFFFFu, p1, o);
    }
    if (lane == 0) {
        out[(size_t)row * 2 + 0] = p0 + bp[0];
        out[(size_t)row * 2 + 1] = p1 + bp[1];
    }
}

// ---------------------------------------------------------------------------
static inline int cdiv(long long a, int b) { return (int)((a + b - 1) / b); }

extern "C" void kernel_launch(void* const* d_in, const int* in_sizes, int n_in,
                              void* d_out, int out_size) {
    const float* x_agent  = (const float*)d_in[1];
    const float* x_target = (const float*)d_in[2];
    const int* src_aa = (const int*)d_in[3];
    const int* dst_aa = (const int*)d_in[4];
    const int* src_at = (const int*)d_in[5];
    const int* dst_at = (const int*)d_in[6];
    const int* src_ta = (const int*)d_in[7];
    const int* dst_ta = (const int*)d_in[8];
    const float* W1_aa = (const float*)d_in[9];
    const float* b1_aa = (const float*)d_in[10];
    const float* W1_at = (const float*)d_in[11];
    const float* b1_at = (const float*)d_in[12];
    const float* W1_ta = (const float*)d_in[13];
    const float* b1_ta = (const float*)d_in[14];
    const float* W2_aa = (const float*)d_in[15];
    const float* b2_aa = (const float*)d_in[16];
    const float* W2_at = (const float*)d_in[17];
    const float* b2_at = (const float*)d_in[18];
    const float* W2_ta = (const float*)d_in[19];
    const float* b2_ta = (const float*)d_in[20];
    const float* Wp_agent  = (const float*)d_in[21];
    const float* bp_agent  = (const float*)d_in[22];
    const float* Wp_target = (const float*)d_in[23];
    const float* bp_target = (const float*)d_in[24];
    float* out = (float*)d_out;

    void *p_dis, *p_haa, *p_hat, *p_hta, *p_acca, *p_acct;
    cudaGetSymbolAddress(&p_dis,  g_dis);
    cudaGetSymbolAddress(&p_haa,  g_h_aa);
    cudaGetSymbolAddress(&p_hat,  g_h_at);
    cudaGetSymbolAddress(&p_hta,  g_h_ta);
    cudaGetSymbolAddress(&p_acca, g_acc_a);
    cudaGetSymbolAddress(&p_acct, g_acc_t);
    float*  dis   = (float*)p_dis;
    float4* h_aa  = (float4*)p_haa;
    float4* h_at  = (float4*)p_hat;
    float4* h_ta  = (float4*)p_hta;
    float4* acc_a = (float4*)p_acca;
    float4* acc_t = (float4*)p_acct;

    // ---- degrees / norms (shared by both layers) ----
    zero_cnt_kernel<<<cdiv(NTOT, 256), 256>>>();
    constexpr long long CNT_TOT = E_AA + 2LL * E_AT + 2LL * E_TA;
    count_all_kernel<<<cdiv(CNT_TOT, 256), 256>>>(dst_aa, src_at, dst_at, src_ta, dst_ta);
    dis_kernel<<<cdiv(NTOT, 256), 256>>>();

    // ---- layer 1 transforms ----
    transform_kernel<DIN, false><<<cdiv(NA, 4), 256>>>(x_agent,  W1_aa, (float*)h_aa, NA);
    transform_kernel<DIN, false><<<cdiv(NA, 4), 256>>>(x_agent,  W1_at, (float*)h_at, NA);
    transform_kernel<DIN, false><<<cdiv(NT, 4), 256>>>(x_target, W1_ta, (float*)h_ta, NT);

    // ---- layer 1 aggregate ----
    init_acc_agent_kernel<<<cdiv((long long)NA * H, 256), 256>>>((float*)h_aa, b1_aa, b1_ta);
    init_acc_target_kernel<<<cdiv((long long)NT * H, 256), 256>>>(b1_at);
    scatter_kernel<<<cdiv((long long)E_AA * 16, 256), 256>>>(
        src_aa, dst_aa, dis + OFF_AA,   dis + OFF_AA,   h_aa, acc_a, E_AA);
    scatter_kernel<<<cdiv((long long)E_TA * 16, 256), 256>>>(
        src_ta, dst_ta, dis + OFF_TA_S, dis + OFF_TA_D, h_ta, acc_a, E_TA);
    scatter_kernel<<<cdiv((long long)E_AT * 16, 256), 256>>>(
        src_at, dst_at, dis + OFF_AT_S, dis + OFF_AT_D, h_at, acc_t, E_AT);

    // ---- layer 2 transforms: relu(acc) @ W2_* ----
    transform_kernel<H, true><<<cdiv(NA, 4), 256>>>((float*)acc_a, W2_aa, (float*)h_aa, NA);
    transform_kernel<H, true><<<cdiv(NA, 4), 256>>>((float*)acc_a, W2_at, (float*)h_at, NA);
    transform_kernel<H, true><<<cdiv(NT, 4), 256>>>((float*)acc_t, W2_ta, (float*)h_ta, NT);

    // ---- layer 2 aggregate ----
    init_acc_agent_kernel<<<cdiv((long long)NA * H, 256), 256>>>((float*)h_aa, b2_aa, b2_ta);
    init_acc_target_kernel<<<cdiv((long long)NT * H, 256), 256>>>(b2_at);
    scatter_kernel<<<cdiv((long long)E_AA * 16, 256), 256>>>(
        src_aa, dst_aa, dis + OFF_AA,   dis + OFF_AA,   h_aa, acc_a, E_AA);
    scatter_kernel<<<cdiv((long long)E_TA * 16, 256), 256>>>(
        src_ta, dst_ta, dis + OFF_TA_S, dis + OFF_TA_D, h_ta, acc_a, E_TA);
    scatter_kernel<<<cdiv((long long)E_AT * 16, 256), 256>>>(
        src_at, dst_at, dis + OFF_AT_S, dis + OFF_AT_D, h_at, acc_t, E_AT);

    // ---- output projections ----
    proj_kernel<<<cdiv((long long)NA * 32, 256), 256>>>((float*)acc_a, Wp_agent,  bp_agent,  out, NA);
    proj_kernel<<<cdiv((long long)NT * 32, 256), 256>>>((float*)acc_t, Wp_target, bp_target, out + (size_t)NA * 2, NT);
}

// round 3
// speedup vs baseline: 1.7987x; 1.4560x over previous
#include <cuda_runtime.h>
#include <math.h>

constexpr int NA = 50000;
constexpr int NT = 25000;
constexpr int DIN = 32;
constexpr int H = 64;
constexpr int E_AA = 800000;
constexpr int E_AT = 400000;
constexpr int E_TA = 400000;

constexpr int OFF_AA   = 0;
constexpr int OFF_AT_S = NA;
constexpr int OFF_TA_D = 2 * NA;
constexpr int OFF_AT_D = 3 * NA;
constexpr int OFF_TA_S = 3 * NA + NT;
constexpr int NTOT = 3 * NA + 2 * NT;

__device__ int    g_cnt[NTOT];
__device__ float  g_dis[NTOT];
__device__ float4 g_h_aa[(size_t)NA * H / 4];
__device__ float4 g_h_at[(size_t)NA * H / 4];
__device__ float4 g_h_ta[(size_t)NT * H / 4];
__device__ float4 g_acc_a[(size_t)NA * H / 4];
__device__ float4 g_acc_t[(size_t)NT * H / 4];

__device__ __forceinline__ void red_add_v4(float4* addr, float4 v) {
    asm volatile("red.global.add.v4.f32 [%0], {%1,%2,%3,%4};"
                 :: "l"(addr), "f"(v.x), "f"(v.y), "f"(v.z), "f"(v.w)
                 : "memory");
}

// ---------------------------------------------------------------------------
__global__ void zero_cnt_kernel() {
    int i = blockIdx.x * blockDim.x + threadIdx.x;
    if (i < NTOT) g_cnt[i] = 0;
}

__global__ void count_all_kernel(const int* __restrict__ dst_aa,
                                 const int* __restrict__ src_at,
                                 const int* __restrict__ dst_at,
                                 const int* __restrict__ src_ta,
                                 const int* __restrict__ dst_ta) {
    int i = blockIdx.x * blockDim.x + threadIdx.x;
    const int* p; int off, j;
    if (i < E_AA)                            { p = dst_aa; off = OFF_AA;   j = i; }
    else if (i < E_AA + E_AT)                { p = src_at; off = OFF_AT_S; j = i - E_AA; }
    else if (i < E_AA + 2 * E_AT)            { p = dst_at; off = OFF_AT_D; j = i - E_AA - E_AT; }
    else if (i < E_AA + 2 * E_AT + E_TA)     { p = src_ta; off = OFF_TA_S; j = i - E_AA - 2 * E_AT; }
    else if (i < E_AA + 2 * E_AT + 2 * E_TA) { p = dst_ta; off = OFF_TA_D; j = i - E_AA - 2 * E_AT - E_TA; }
    else return;
    atomicAdd(&g_cnt[off + p[j]], 1);
}

__global__ void dis_kernel() {
    int i = blockIdx.x * blockDim.x + threadIdx.x;
    if (i >= NTOT) return;
    int c = g_cnt[i];
    float d;
    if (i < NA) d = rsqrtf((float)c + 1.0f);
    else        d = (c > 0) ? rsqrtf((float)c) : 0.0f;
    g_dis[i] = d;
}

// Dual-weight register-tiled transform: outa = act(x)@Wa, outb = act(x)@Wb
// BM=64 rows/block, 128 output cols (64 per weight), 256 threads, TM=4, TN=8.
template <int K, bool RELU>
__global__ __launch_bounds__(256) void transform2_kernel(
        const float4* __restrict__ x,
        const float* __restrict__ Wa, const float* __restrict__ Wb,
        float* __restrict__ outa, float* __restrict__ outb, int n) {
    __shared__ float xs[64][K];
    __shared__ float Ws[K][128];
    int tid = threadIdx.x;
    int row0 = blockIdx.x * 64;
    for (int i = tid; i < K * 64; i += 256) {
        int k = i >> 6, c = i & 63;
        Ws[k][c]      = Wa[i];
        Ws[k][c + 64] = Wb[i];
    }
    constexpr int KV = K / 4;
    for (int i = tid; i < 64 * KV; i += 256) {
        int r = i / KV, kv = i - r * KV;
        int row = row0 + r;
        float4 v = (row < n) ? x[(size_t)row * KV + kv] : make_float4(0.f, 0.f, 0.f, 0.f);
        if (RELU) { v.x = fmaxf(v.x, 0.f); v.y = fmaxf(v.y, 0.f);
                    v.z = fmaxf(v.z, 0.f); v.w = fmaxf(v.w, 0.f); }
        *(float4*)&xs[r][kv * 4] = v;
    }
    __syncthreads();
    int ty = tid >> 4, tx = tid & 15;
    int r0 = ty * 4, c0 = tx * 8;
    float acc[4][8];
#pragma unroll
    for (int i = 0; i < 4; i++)
#pragma unroll
        for (int j = 0; j < 8; j++) acc[i][j] = 0.f;
#pragma unroll 4
    for (int k = 0; k < K; k++) {
        float w[8];
        *(float4*)&w[0] = *(float4*)&Ws[k][c0];
        *(float4*)&w[4] = *(float4*)&Ws[k][c0 + 4];
#pragma unroll
        for (int i = 0; i < 4; i++) {
            float xv = xs[r0 + i][k];
#pragma unroll
            for (int j = 0; j < 8; j++) acc[i][j] = fmaf(xv, w[j], acc[i][j]);
        }
    }
#pragma unroll
    for (int i = 0; i < 4; i++) {
        int row = row0 + r0 + i;
        if (row < n) {
            float* dst = (c0 < 64) ? (outa + (size_t)row * 64 + c0)
                                   : (outb + (size_t)row * 64 + (c0 - 64));
            *(float4*)dst       = *(float4*)&acc[i][0];
            *(float4*)(dst + 4) = *(float4*)&acc[i][4];
        }
    }
}

// Single-weight tiled transform: out = act(x)@W. BM=64, 64 cols, 256 thr, TM=4, TN=4.
template <int K, bool RELU>
__global__ __launch_bounds__(256) void transform1_kernel(
        const float4* __restrict__ x, const float* __restrict__ W,
        float* __restrict__ out, int n) {
    __shared__ float xs[64][K];
    __shared__ float Ws[K][64];
    int tid = threadIdx.x;
    int row0 = blockIdx.x * 64;
    for (int i = tid; i < K * 64; i += 256) {
        int k = i >> 6, c = i & 63;
        Ws[k][c] = W[i];
    }
    constexpr int KV = K / 4;
    for (int i = tid; i < 64 * KV; i += 256) {
        int r = i / KV, kv = i - r * KV;
        int row = row0 + r;
        float4 v = (row < n) ? x[(size_t)row * KV + kv] : make_float4(0.f, 0.f, 0.f, 0.f);
        if (RELU) { v.x = fmaxf(v.x, 0.f); v.y = fmaxf(v.y, 0.f);
                    v.z = fmaxf(v.z, 0.f); v.w = fmaxf(v.w, 0.f); }
        *(float4*)&xs[r][kv * 4] = v;
    }
    __syncthreads();
    int ty = tid >> 4, tx = tid & 15;
    int r0 = ty * 4, c0 = tx * 4;
    float acc[4][4];
#pragma unroll
    for (int i = 0; i < 4; i++)
#pragma unroll
        for (int j = 0; j < 4; j++) acc[i][j] = 0.f;
#pragma unroll 4
    for (int k = 0; k < K; k++) {
        float w[4];
        *(float4*)&w[0] = *(float4*)&Ws[k][c0];
#pragma unroll
        for (int i = 0; i < 4; i++) {
            float xv = xs[r0 + i][k];
#pragma unroll
            for (int j = 0; j < 4; j++) acc[i][j] = fmaf(xv, w[j], acc[i][j]);
        }
    }
#pragma unroll
    for (int i = 0; i < 4; i++) {
        int row = row0 + r0 + i;
        if (row < n) *(float4*)(out + (size_t)row * 64 + c0) = *(float4*)&acc[i][0];
    }
}

// acc_a[i,:] = h_self[i,:] * dis_aa[i]^2 + b_self + b_other   (float4)
__global__ void init_acc_agent_kernel(const float4* __restrict__ h_self,
                                      const float* __restrict__ b_self,
                                      const float* __restrict__ b_other) {
    int i = blockIdx.x * blockDim.x + threadIdx.x;
    if (i >= NA * (H / 4)) return;
    int node = i >> 4, cv = (i & 15) * 4;
    float d = g_dis[OFF_AA + node];
    float dd = d * d;
    float4 h = h_self[i];
    float4 o;
    o.x = h.x * dd + b_self[cv + 0] + b_other[cv + 0];
    o.y = h.y * dd + b_self[cv + 1] + b_other[cv + 1];
    o.z = h.z * dd + b_self[cv + 2] + b_other[cv + 2];
    o.w = h.w * dd + b_self[cv + 3] + b_other[cv + 3];
    g_acc_a[i] = o;
}

__global__ void init_acc_target_kernel(const float* __restrict__ b) {
    int i = blockIdx.x * blockDim.x + threadIdx.x;
    if (i >= NT * (H / 4)) return;
    int cv = (i & 15) * 4;
    g_acc_t[i] = make_float4(b[cv], b[cv + 1], b[cv + 2], b[cv + 3]);
}

// 16 lanes per edge: one float4 gather + red.v4 per lane
__global__ void scatter_kernel(const int* __restrict__ src,
                               const int* __restrict__ dst,
                               const float* __restrict__ dis_s,
                               const float* __restrict__ dis_d,
                               const float4* __restrict__ h,
                               float4* __restrict__ acc, int E) {
    int idx = blockIdx.x * blockDim.x + threadIdx.x;
    int e = idx >> 4, sub = idx & 15;
    if (e >= E) return;
    int s = src[e], d = dst[e];
    float w = dis_s[s] * dis_d[d];
    float4 v = h[(size_t)s * (H / 4) + sub];
    v.x *= w; v.y *= w; v.z *= w; v.w *= w;
    red_add_v4(&acc[(size_t)d * (H / 4) + sub], v);
}

// One warp per row: out[row,:] = g[row,:] @ Wp + bp   (Wp is [H,2])
__global__ void proj_kernel(const float* __restrict__ g,
                            const float* __restrict__ Wp,
                            const float* __restrict__ bp,
                            float* __restrict__ out, int n) {
    int idx = blockIdx.x * blockDim.x + threadIdx.x;
    int row = idx >> 5, lane = idx & 31;
    if (row >= n) return;
    float g0 = g[(size_t)row * H + lane];
    float g1 = g[(size_t)row * H + lane + 32];
    float p0 = g0 * Wp[lane * 2 + 0] + g1 * Wp[(lane + 32) * 2 + 0];
    float p1 = g0 * Wp[lane * 2 + 1] + g1 * Wp[(lane + 32) * 2 + 1];
#pragma unroll
    for (int o = 16; o; o >>= 1) {
        p0 += __shfl_down_sync(0xFFFFFFFFu, p0, o);
        p1 += __shfl_down_sync(0xFFFFFFFFu, p1, o);
    }
    if (lane == 0) {
        out[(size_t)row * 2 + 0] = p0 + bp[0];
        out[(size_t)row * 2 + 1] = p1 + bp[1];
    }
}

// ---------------------------------------------------------------------------
static inline int cdiv(long long a, int b) { return (int)((a + b - 1) / b); }

extern "C" void kernel_launch(void* const* d_in, const int* in_sizes, int n_in,
                              void* d_out, int out_size) {
    const float* x_agent  = (const float*)d_in[1];
    const float* x_target = (const float*)d_in[2];
    const int* src_aa = (const int*)d_in[3];
    const int* dst_aa = (const int*)d_in[4];
    const int* src_at = (const int*)d_in[5];
    const int* dst_at = (const int*)d_in[6];
    const int* src_ta = (const int*)d_in[7];
    const int* dst_ta = (const int*)d_in[8];
    const float* W1_aa = (const float*)d_in[9];
    const float* b1_aa = (const float*)d_in[10];
    const float* W1_at = (const float*)d_in[11];
    const float* b1_at = (const float*)d_in[12];
    const float* W1_ta = (const float*)d_in[13];
    const float* b1_ta = (const float*)d_in[14];
    const float* W2_aa = (const float*)d_in[15];
    const float* b2_aa = (const float*)d_in[16];
    const float* W2_at = (const float*)d_in[17];
    const float* b2_at = (const float*)d_in[18];
    const float* W2_ta = (const float*)d_in[19];
    const float* b2_ta = (const float*)d_in[20];
    const float* Wp_agent  = (const float*)d_in[21];
    const float* bp_agent  = (const float*)d_in[22];
    const float* Wp_target = (const float*)d_in[23];
    const float* bp_target = (const float*)d_in[24];
    float* out = (float*)d_out;

    void *p_dis, *p_haa, *p_hat, *p_hta, *p_acca, *p_acct;
    cudaGetSymbolAddress(&p_dis,  g_dis);
    cudaGetSymbolAddress(&p_haa,  g_h_aa);
    cudaGetSymbolAddress(&p_hat,  g_h_at);
    cudaGetSymbolAddress(&p_hta,  g_h_ta);
    cudaGetSymbolAddress(&p_acca, g_acc_a);
    cudaGetSymbolAddress(&p_acct, g_acc_t);
    float*  dis   = (float*)p_dis;
    float4* h_aa  = (float4*)p_haa;
    float4* h_at  = (float4*)p_hat;
    float4* h_ta  = (float4*)p_hta;
    float4* acc_a = (float4*)p_acca;
    float4* acc_t = (float4*)p_acct;

    // ---- degrees / norms ----
    zero_cnt_kernel<<<cdiv(NTOT, 256), 256>>>();
    constexpr long long CNT_TOT = E_AA + 2LL * E_AT + 2LL * E_TA;
    count_all_kernel<<<cdiv(CNT_TOT, 256), 256>>>(dst_aa, src_at, dst_at, src_ta, dst_ta);
    dis_kernel<<<cdiv(NTOT, 256), 256>>>();

    // ---- layer 1 transforms ----
    transform2_kernel<DIN, false><<<cdiv(NA, 64), 256>>>(
        (const float4*)x_agent, W1_aa, W1_at, (float*)h_aa, (float*)h_at, NA);
    transform1_kernel<DIN, false><<<cdiv(NT, 64), 256>>>(
        (const float4*)x_target, W1_ta, (float*)h_ta, NT);

    // ---- layer 1 aggregate ----
    init_acc_agent_kernel<<<cdiv((long long)NA * H / 4, 256), 256>>>(h_aa, b1_aa, b1_ta);
    init_acc_target_kernel<<<cdiv((long long)NT * H / 4, 256), 256>>>(b1_at);
    scatter_kernel<<<cdiv((long long)E_AA * 16, 256), 256>>>(
        src_aa, dst_aa, dis + OFF_AA,   dis + OFF_AA,   h_aa, acc_a, E_AA);
    scatter_kernel<<<cdiv((long long)E_TA * 16, 256), 256>>>(
        src_ta, dst_ta, dis + OFF_TA_S, dis + OFF_TA_D, h_ta, acc_a, E_TA);
    scatter_kernel<<<cdiv((long long)E_AT * 16, 256), 256>>>(
        src_at, dst_at, dis + OFF_AT_S, dis + OFF_AT_D, h_at, acc_t, E_AT);

    // ---- layer 2 transforms: relu(acc) @ W2_* ----
    transform2_kernel<H, true><<<cdiv(NA, 64), 256>>>(
        (const float4*)acc_a, W2_aa, W2_at, (float*)h_aa, (float*)h_at, NA);
    transform1_kernel<H, true><<<cdiv(NT, 64), 256>>>(
        (const float4*)acc_t, W2_ta, (float*)h_ta, NT);

    // ---- layer 2 aggregate ----
    init_acc_agent_kernel<<<cdiv((long long)NA * H / 4, 256), 256>>>(h_aa, b2_aa, b2_ta);
    init_acc_target_kernel<<<cdiv((long long)NT * H / 4, 256), 256>>>(b2_at);
    scatter_kernel<<<cdiv((long long)E_AA * 16, 256), 256>>>(
        src_aa, dst_aa, dis + OFF_AA,   dis + OFF_AA,   h_aa, acc_a, E_AA);
    scatter_kernel<<<cdiv((long long)E_TA * 16, 256), 256>>>(
        src_ta, dst_ta, dis + OFF_TA_S, dis + OFF_TA_D, h_ta, acc_a, E_TA);
    scatter_kernel<<<cdiv((long long)E_AT * 16, 256), 256>>>(
        src_at, dst_at, dis + OFF_AT_S, dis + OFF_AT_D, h_at, acc_t, E_AT);

    // ---- output projections ----
    proj_kernel<<<cdiv((long long)NA * 32, 256), 256>>>((float*)acc_a, Wp_agent,  bp_agent,  out, NA);
    proj_kernel<<<cdiv((long long)NT * 32, 256), 256>>>((float*)acc_t, Wp_target, bp_target, out + (size_t)NA * 2, NT);
}

// round 4
// speedup vs baseline: 1.9595x; 1.0894x over previous
#include <cuda_runtime.h>
#include <cuda_fp16.h>
#include <math.h>

constexpr int NA = 50000;
constexpr int NT = 25000;
constexpr int DIN = 32;
constexpr int H = 64;
constexpr int E_AA = 800000;
constexpr int E_AT = 400000;
constexpr int E_TA = 400000;

constexpr int OFF_AA   = 0;
constexpr int OFF_AT_S = NA;
constexpr int OFF_TA_D = 2 * NA;
constexpr int OFF_AT_D = 3 * NA;
constexpr int OFF_TA_S = 3 * NA + NT;
constexpr int NTOT = 3 * NA + 2 * NT;

__device__ int    g_cnt[NTOT];
__device__ float  g_dis[NTOT];
__device__ __half g_h16_aa[(size_t)NA * H];
__device__ __half g_h16_at[(size_t)NA * H];
__device__ __half g_h16_ta[(size_t)NT * H];
__device__ float4 g_acc_a[(size_t)NA * H / 4];
__device__ float4 g_acc_t[(size_t)NT * H / 4];

__device__ __forceinline__ void red_add_v4(float4* addr, float4 v) {
    asm volatile("red.global.add.v4.f32 [%0], {%1,%2,%3,%4};"
                 :: "l"(addr), "f"(v.x), "f"(v.y), "f"(v.z), "f"(v.w)
                 : "memory");
}

__device__ __forceinline__ uint4 pack_half8(const float* a) {
    __half2 h0 = __floats2half2_rn(a[0], a[1]);
    __half2 h1 = __floats2half2_rn(a[2], a[3]);
    __half2 h2 = __floats2half2_rn(a[4], a[5]);
    __half2 h3 = __floats2half2_rn(a[6], a[7]);
    uint4 u;
    u.x = *(unsigned*)&h0; u.y = *(unsigned*)&h1;
    u.z = *(unsigned*)&h2; u.w = *(unsigned*)&h3;
    return u;
}

// ---------------------------------------------------------------------------
__global__ void zero_cnt_kernel() {
    int i = blockIdx.x * blockDim.x + threadIdx.x;
    if (i < NTOT) g_cnt[i] = 0;
}

__global__ void count_all_kernel(const int* __restrict__ dst_aa,
                                 const int* __restrict__ src_at,
                                 const int* __restrict__ dst_at,
                                 const int* __restrict__ src_ta,
                                 const int* __restrict__ dst_ta) {
    int i = blockIdx.x * blockDim.x + threadIdx.x;
    const int* p; int off, j;
    if (i < E_AA)                            { p = dst_aa; off = OFF_AA;   j = i; }
    else if (i < E_AA + E_AT)                { p = src_at; off = OFF_AT_S; j = i - E_AA; }
    else if (i < E_AA + 2 * E_AT)            { p = dst_at; off = OFF_AT_D; j = i - E_AA - E_AT; }
    else if (i < E_AA + 2 * E_AT + E_TA)     { p = src_ta; off = OFF_TA_S; j = i - E_AA - 2 * E_AT; }
    else if (i < E_AA + 2 * E_AT + 2 * E_TA) { p = dst_ta; off = OFF_TA_D; j = i - E_AA - 2 * E_AT - E_TA; }
    else return;
    atomicAdd(&g_cnt[off + p[j]], 1);
}

__global__ void dis_kernel() {
    int i = blockIdx.x * blockDim.x + threadIdx.x;
    if (i >= NTOT) return;
    int c = g_cnt[i];
    float d;
    if (i < NA) d = rsqrtf((float)c + 1.0f);
    else        d = (c > 0) ? rsqrtf((float)c) : 0.0f;
    g_dis[i] = d;
}

// Agent transform, fused epilogue:
//   haa = act(x)@Wa -> g_h16_aa (fp16)  and  g_acc_a = haa*dis_aa^2 + b_aa + b_ta (fp32)
//   hat = act(x)@Wb -> g_h16_at (fp16)
// BM=64 rows, 128 cols, 256 threads, TM=4, TN=8. Layer2 reads/writes g_acc_a in place (safe:
// each row is loaded to smem by its own block before that block's epilogue writes it).
template <int K, bool RELU>
__global__ __launch_bounds__(256, 3) void transform_agent_kernel(
        const float4* __restrict__ x,
        const float* __restrict__ Wa, const float* __restrict__ Wb,
        const float* __restrict__ b_aa, const float* __restrict__ b_ta) {
    __shared__ float xs[64][K];
    __shared__ float Ws[K][128];
    __shared__ float bsum[64];
    int tid = threadIdx.x;
    int row0 = blockIdx.x * 64;
    for (int i = tid; i < K * 64; i += 256) {
        int k = i >> 6, c = i & 63;
        Ws[k][c]      = Wa[i];
        Ws[k][c + 64] = Wb[i];
    }
    if (tid < 64) bsum[tid] = b_aa[tid] + b_ta[tid];
    constexpr int KV = K / 4;
    for (int i = tid; i < 64 * KV; i += 256) {
        int r = i / KV, kv = i - r * KV;
        int row = row0 + r;
        float4 v = (row < NA) ? x[(size_t)row * KV + kv] : make_float4(0.f, 0.f, 0.f, 0.f);
        if (RELU) { v.x = fmaxf(v.x, 0.f); v.y = fmaxf(v.y, 0.f);
                    v.z = fmaxf(v.z, 0.f); v.w = fmaxf(v.w, 0.f); }
        *(float4*)&xs[r][kv * 4] = v;
    }
    __syncthreads();
    int ty = tid >> 4, tx = tid & 15;
    int r0 = ty * 4, c0 = tx * 8;
    float acc[4][8];
#pragma unroll
    for (int i = 0; i < 4; i++)
#pragma unroll
        for (int j = 0; j < 8; j++) acc[i][j] = 0.f;
#pragma unroll 4
    for (int k = 0; k < K; k++) {
        float w[8];
        *(float4*)&w[0] = *(float4*)&Ws[k][c0];
        *(float4*)&w[4] = *(float4*)&Ws[k][c0 + 4];
#pragma unroll
        for (int i = 0; i < 4; i++) {
            float xv = xs[r0 + i][k];
#pragma unroll
            for (int j = 0; j < 8; j++) acc[i][j] = fmaf(xv, w[j], acc[i][j]);
        }
    }
    bool is_a = (c0 < 64);
    int cc = is_a ? c0 : (c0 - 64);
#pragma unroll
    for (int i = 0; i < 4; i++) {
        int row = row0 + r0 + i;
        if (row >= NA) continue;
        uint4 hpk = pack_half8(&acc[i][0]);
        if (is_a) {
            *(uint4*)(g_h16_aa + (size_t)row * H + cc) = hpk;
            float d = g_dis[OFF_AA + row];
            float dd = d * d;
            float4 o0, o1;
            o0.x = acc[i][0] * dd + bsum[cc + 0];
            o0.y = acc[i][1] * dd + bsum[cc + 1];
            o0.z = acc[i][2] * dd + bsum[cc + 2];
            o0.w = acc[i][3] * dd + bsum[cc + 3];
            o1.x = acc[i][4] * dd + bsum[cc + 4];
            o1.y = acc[i][5] * dd + bsum[cc + 5];
            o1.z = acc[i][6] * dd + bsum[cc + 6];
            o1.w = acc[i][7] * dd + bsum[cc + 7];
            g_acc_a[(size_t)row * (H / 4) + (cc >> 2)]     = o0;
            g_acc_a[(size_t)row * (H / 4) + (cc >> 2) + 1] = o1;
        } else {
            *(uint4*)(g_h16_at + (size_t)row * H + cc) = hpk;
        }
    }
}

// Target transform: g_h16_ta = act(x)@W (fp16 out). BM=64, 64 cols, 256 thr, TM=4, TN=4.
template <int K, bool RELU>
__global__ __launch_bounds__(256, 3) void transform_target_kernel(
        const float4* __restrict__ x, const float* __restrict__ W) {
    __shared__ float xs[64][K];
    __shared__ float Ws[K][64];
    int tid = threadIdx.x;
    int row0 = blockIdx.x * 64;
    for (int i = tid; i < K * 64; i += 256) {
        int k = i >> 6, c = i & 63;
        Ws[k][c] = W[i];
    }
    constexpr int KV = K / 4;
    for (int i = tid; i < 64 * KV; i += 256) {
        int r = i / KV, kv = i - r * KV;
        int row = row0 + r;
        float4 v = (row < NT) ? x[(size_t)row * KV + kv] : make_float4(0.f, 0.f, 0.f, 0.f);
        if (RELU) { v.x = fmaxf(v.x, 0.f); v.y = fmaxf(v.y, 0.f);
                    v.z = fmaxf(v.z, 0.f); v.w = fmaxf(v.w, 0.f); }
        *(float4*)&xs[r][kv * 4] = v;
    }
    __syncthreads();
    int ty = tid >> 4, tx = tid & 15;
    int r0 = ty * 4, c0 = tx * 4;
    float acc[4][4];
#pragma unroll
    for (int i = 0; i < 4; i++)
#pragma unroll
        for (int j = 0; j < 4; j++) acc[i][j] = 0.f;
#pragma unroll 4
    for (int k = 0; k < K; k++) {
        float w[4];
        *(float4*)&w[0] = *(float4*)&Ws[k][c0];
#pragma unroll
        for (int i = 0; i < 4; i++) {
            float xv = xs[r0 + i][k];
#pragma unroll
            for (int j = 0; j < 4; j++) acc[i][j] = fmaf(xv, w[j], acc[i][j]);
        }
    }
#pragma unroll
    for (int i = 0; i < 4; i++) {
        int row = row0 + r0 + i;
        if (row >= NT) continue;
        __half2 h0 = __floats2half2_rn(acc[i][0], acc[i][1]);
        __half2 h1 = __floats2half2_rn(acc[i][2], acc[i][3]);
        uint2 u; u.x = *(unsigned*)&h0; u.y = *(unsigned*)&h1;
        *(uint2*)(g_h16_ta + (size_t)row * H + c0) = u;
    }
}

__global__ void init_acc_target_kernel(const float* __restrict__ b) {
    int i = blockIdx.x * blockDim.x + threadIdx.x;
    if (i >= NT * (H / 4)) return;
    int cv = (i & 15) * 4;
    g_acc_t[i] = make_float4(b[cv], b[cv + 1], b[cv + 2], b[cv + 3]);
}

// Fused scatter for all 3 relations of one layer. 16 lanes/edge; lane sub==0 loads
// src/dst/norm, broadcasts via shfl; each lane gathers 4 fp16 feats, red.v4 fp32.
__global__ void scatter_all_kernel(const int* __restrict__ src_aa, const int* __restrict__ dst_aa,
                                   const int* __restrict__ src_ta, const int* __restrict__ dst_ta,
                                   const int* __restrict__ src_at, const int* __restrict__ dst_at) {
    int idx = blockIdx.x * blockDim.x + threadIdx.x;
    int e = idx >> 4, sub = idx & 15;
    int lane = threadIdx.x & 31;
    const __half* h; float4* acc;
    const int* sp; const int* dp; int offs, offd, j;
    if (e < E_AA) {
        j = e; sp = src_aa; dp = dst_aa; offs = OFF_AA; offd = OFF_AA;
        h = g_h16_aa; acc = g_acc_a;
    } else if (e < E_AA + E_TA) {
        j = e - E_AA; sp = src_ta; dp = dst_ta; offs = OFF_TA_S; offd = OFF_TA_D;
        h = g_h16_ta; acc = g_acc_a;
    } else if (e < E_AA + E_TA + E_AT) {
        j = e - E_AA - E_TA; sp = src_at; dp = dst_at; offs = OFF_AT_S; offd = OFF_AT_D;
        h = g_h16_at; acc = g_acc_t;
    } else return;
    int s = 0, d = 0; float w = 0.f;
    if (sub == 0) {
        s = sp[j]; d = dp[j];
        w = g_dis[offs + s] * g_dis[offd + d];
    }
    int srclane = lane & 16;
    s = __shfl_sync(0xFFFFFFFFu, s, srclane);
    d = __shfl_sync(0xFFFFFFFFu, d, srclane);
    w = __shfl_sync(0xFFFFFFFFu, w, srclane);
    uint2 raw = *(const uint2*)(h + (size_t)s * H + sub * 4);
    __half2 a0 = *(__half2*)&raw.x;
    __half2 a1 = *(__half2*)&raw.y;
    float2 f0 = __half22float2(a0);
    float2 f1 = __half22float2(a1);
    float4 v = make_float4(f0.x * w, f0.y * w, f1.x * w, f1.y * w);
    red_add_v4(&acc[(size_t)d * (H / 4) + sub], v);
}

// One warp per row: out[row,:] = g[row,:] @ Wp + bp   (Wp is [H,2])
__global__ void proj_kernel(const float* __restrict__ g,
                            const float* __restrict__ Wp,
                            const float* __restrict__ bp,
                            float* __restrict__ out, int n) {
    int idx = blockIdx.x * blockDim.x + threadIdx.x;
    int row = idx >> 5, lane = idx & 31;
    if (row >= n) return;
    float g0 = g[(size_t)row * H + lane];
    float g1 = g[(size_t)row * H + lane + 32];
    float p0 = g0 * Wp[lane * 2 + 0] + g1 * Wp[(lane + 32) * 2 + 0];
    float p1 = g0 * Wp[lane * 2 + 1] + g1 * Wp[(lane + 32) * 2 + 1];
#pragma unroll
    for (int o = 16; o; o >>= 1) {
        p0 += __shfl_down_sync(0xFFFFFFFFu, p0, o);
        p1 += __shfl_down_sync(0xFFFFFFFFu, p1, o);
    }
    if (lane == 0) {
        out[(size_t)row * 2 + 0] = p0 + bp[0];
        out[(size_t)row * 2 + 1] = p1 + bp[1];
    }
}

// ---------------------------------------------------------------------------
static inline int cdiv(long long a, int b) { return (int)((a + b - 1) / b); }

extern "C" void kernel_launch(void* const* d_in, const int* in_sizes, int n_in,
                              void* d_out, int out_size) {
    const float* x_agent  = (const float*)d_in[1];
    const float* x_target = (const float*)d_in[2];
    const int* src_aa = (const int*)d_in[3];
    const int* dst_aa = (const int*)d_in[4];
    const int* src_at = (const int*)d_in[5];
    const int* dst_at = (const int*)d_in[6];
    const int* src_ta = (const int*)d_in[7];
    const int* dst_ta = (const int*)d_in[8];
    const float* W1_aa = (const float*)d_in[9];
    const float* b1_aa = (const float*)d_in[10];
    const float* W1_at = (const float*)d_in[11];
    const float* b1_at = (const float*)d_in[12];
    const float* W1_ta = (const float*)d_in[13];
    const float* b1_ta = (const float*)d_in[14];
    const float* W2_aa = (const float*)d_in[15];
    const float* b2_aa = (const float*)d_in[16];
    const float* W2_at = (const float*)d_in[17];
    const float* b2_at = (const float*)d_in[18];
    const float* W2_ta = (const float*)d_in[19];
    const float* b2_ta = (const float*)d_in[20];
    const float* Wp_agent  = (const float*)d_in[21];
    const float* bp_agent  = (const float*)d_in[22];
    const float* Wp_target = (const float*)d_in[23];
    const float* bp_target = (const float*)d_in[24];
    float* out = (float*)d_out;

    void *p_acca, *p_acct;
    cudaGetSymbolAddress(&p_acca, g_acc_a);
    cudaGetSymbolAddress(&p_acct, g_acc_t);
    float* acc_a = (float*)p_acca;
    float* acc_t = (float*)p_acct;

    // ---- degrees / norms ----
    zero_cnt_kernel<<<cdiv(NTOT, 256), 256>>>();
    constexpr long long CNT_TOT = E_AA + 2LL * E_AT + 2LL * E_TA;
    count_all_kernel<<<cdiv(CNT_TOT, 256), 256>>>(dst_aa, src_at, dst_at, src_ta, dst_ta);
    dis_kernel<<<cdiv(NTOT, 256), 256>>>();

    constexpr long long SC_TOT = (long long)(E_AA + E_TA + E_AT) * 16;

    // ---- layer 1 ----
    transform_agent_kernel<DIN, false><<<cdiv(NA, 64), 256>>>(
        (const float4*)x_agent, W1_aa, W1_at, b1_aa, b1_ta);
    transform_target_kernel<DIN, false><<<cdiv(NT, 64), 256>>>(
        (const float4*)x_target, W1_ta);
    init_acc_target_kernel<<<cdiv((long long)NT * H / 4, 256), 256>>>(b1_at);
    scatter_all_kernel<<<cdiv(SC_TOT, 256), 256>>>(src_aa, dst_aa, src_ta, dst_ta, src_at, dst_at);

    // ---- layer 2 ----
    transform_agent_kernel<H, true><<<cdiv(NA, 64), 256>>>(
        (const float4*)acc_a, W2_aa, W2_at, b2_aa, b2_ta);
    transform_target_kernel<H, true><<<cdiv(NT, 64), 256>>>(
        (const float4*)acc_t, W2_ta);
    init_acc_target_kernel<<<cdiv((long long)NT * H / 4, 256), 256>>>(b2_at);
    scatter_all_kernel<<<cdiv(SC_TOT, 256), 256>>>(src_aa, dst_aa, src_ta, dst_ta, src_at, dst_at);

    // ---- output projections ----
    proj_kernel<<<cdiv((long long)NA * 32, 256), 256>>>(acc_a, Wp_agent,  bp_agent,  out, NA);
    proj_kernel<<<cdiv((long long)NT * 32, 256), 256>>>(acc_t, Wp_target, bp_target, out + (size_t)NA * 2, NT);
}